// round 2
// baseline (speedup 1.0000x reference)
#include <cuda_runtime.h>
#include <cuda_bf16.h>

#define NMAX 50000
#define EMAX 800000
#define F_IN 128
#define F_OUT 64

// ---- device scratch (no allocations allowed) ----
__device__ float g_h[NMAX * F_OUT];          // h = x @ W
__device__ float g_as[NMAX];                 // h . a1
__device__ float g_ad[NMAX];                 // h . a2
__device__ float g_m[NMAX];                  // max(seg_max, 0)
__device__ float g_sum[NMAX];                // segment sum of exp
__device__ float g_deg[NMAX];                // degree (float)
__device__ float g_invd[NMAX];               // 1/denom
__device__ float g_logit[EMAX];              // logit, then overwritten with exp_l
__device__ int   g_src[EMAX];                // normalized src indices (int32)
__device__ int   g_dst[EMAX];                // normalized dst indices (int32)
__device__ int   g_flag;                     // 0 = edge buffer is int64, nonzero = int32

// ---------------------------------------------------------------------------
// K0: zero the per-node accumulators + the dtype flag
// ---------------------------------------------------------------------------
__global__ void k_zero(int N) {
    int i = blockIdx.x * blockDim.x + threadIdx.x;
    if (i == 0) g_flag = 0;
    if (i < N) {
        g_m[i] = 0.f;
        g_sum[i] = 0.f;
        g_deg[i] = 0.f;
    }
}

// ---------------------------------------------------------------------------
// K-detect: decide whether the edge buffer is int64 or int32.
// int64 layout: odd 32-bit words are the (zero) high halves of indices.
// int32 layout: odd words are real indices, essentially never all zero.
// ---------------------------------------------------------------------------
__global__ void k_detect(const unsigned int* __restrict__ raw) {
    int t = threadIdx.x;                    // 256 threads, 1 block
    if (raw[2 * t + 1] != 0u)
        atomicOr(&g_flag, 1);
}

// ---------------------------------------------------------------------------
// K-norm: materialize int32 src/dst regardless of source dtype.
// ---------------------------------------------------------------------------
__global__ void k_norm(const void* __restrict__ raw, int E) {
    int e = blockIdx.x * blockDim.x + threadIdx.x;
    if (e >= E) return;
    int s, d;
    if (g_flag == 0) {                      // int64 source
        const long long* p = (const long long*)raw;
        s = (int)p[e];
        d = (int)p[E + e];
    } else {                                // int32 source
        const int* p = (const int*)raw;
        s = p[e];
        d = p[E + e];
    }
    g_src[e] = s;
    g_dst[e] = d;
}

// ---------------------------------------------------------------------------
// K1: h = x @ W    (N x 128) @ (128 x 64)
// 256 threads, 16 rows/block. W staged in smem as float4 [k][cg] (32 KB);
// x tile transposed + padded (stride 17, conflict-free).
// ---------------------------------------------------------------------------
__global__ void k_gemm(const float* __restrict__ x, const float* __restrict__ W, int N) {
    __shared__ float4 Ws[F_IN * 16];       // 32768 B
    __shared__ float  xs[F_IN][17];        // 8704 B
    int tid = threadIdx.x;

    const float4* W4 = (const float4*)W;   // W row-major [128][64]
    #pragma unroll
    for (int i = tid; i < F_IN * 16; i += 256) Ws[i] = W4[i];

    int row0 = blockIdx.x * 16;
    for (int i = tid; i < 16 * F_IN; i += 256) {
        int r = i >> 7;          // 0..15
        int k = i & 127;         // 0..127 (coalesced)
        float v = (row0 + r < N) ? x[(size_t)(row0 + r) * F_IN + k] : 0.f;
        xs[k][r] = v;
    }
    __syncthreads();

    int cg = tid & 15;           // 4-col group
    int rg = tid >> 4;           // row in tile
    float4 acc = make_float4(0.f, 0.f, 0.f, 0.f);
    #pragma unroll 16
    for (int k = 0; k < F_IN; k++) {
        float4 w = Ws[k * 16 + cg];
        float xv = xs[k][rg];
        acc.x += xv * w.x;
        acc.y += xv * w.y;
        acc.z += xv * w.z;
        acc.w += xv * w.w;
    }
    int row = row0 + rg;
    if (row < N)
        *(float4*)&g_h[(size_t)row * F_OUT + cg * 4] = acc;
}

// ---------------------------------------------------------------------------
// K2: per-node attention coefficients: as = h.a1, ad = h.a2 (one warp/node)
// ---------------------------------------------------------------------------
__global__ void k_alpha(const float* __restrict__ att, int N) {
    int gt = blockIdx.x * blockDim.x + threadIdx.x;
    int node = gt >> 5;
    int lane = gt & 31;
    if (node >= N) return;
    float2 hv = *(const float2*)&g_h[(size_t)node * F_OUT + lane * 2];
    float a1x = att[lane * 2], a1y = att[lane * 2 + 1];
    float a2x = att[F_OUT + lane * 2], a2y = att[F_OUT + lane * 2 + 1];
    float s = hv.x * a1x + hv.y * a1y;
    float d = hv.x * a2x + hv.y * a2y;
    #pragma unroll
    for (int o = 16; o; o >>= 1) {
        s += __shfl_down_sync(0xFFFFFFFFu, s, o);
        d += __shfl_down_sync(0xFFFFFFFFu, d, o);
    }
    if (lane == 0) {
        g_as[node] = s;
        g_ad[node] = d;
    }
}

// ---------------------------------------------------------------------------
// K3: per-edge logit + segment max.
// m = max(seg_max, 0): init 0, atomicMax only on positive logits
// (non-negative floats order identically as ints).
// ---------------------------------------------------------------------------
__global__ void k_edge1(int E) {
    int e = blockIdx.x * blockDim.x + threadIdx.x;
    if (e >= E) return;
    int s = g_src[e];
    int d = g_dst[e];
    float l = g_as[s] + g_ad[d];
    l = (l > 0.f) ? l : 0.2f * l;        // leaky_relu(0.2)
    g_logit[e] = l;
    if (l > 0.f)
        atomicMax((int*)&g_m[d], __float_as_int(l));
}

// ---------------------------------------------------------------------------
// K4: exp + segment sum + degree. Overwrites g_logit with exp_l.
// ---------------------------------------------------------------------------
__global__ void k_edge2(int E) {
    int e = blockIdx.x * blockDim.x + threadIdx.x;
    if (e >= E) return;
    int d = g_dst[e];
    float el = __expf(g_logit[e] - g_m[d]);
    g_logit[e] = el;
    atomicAdd(&g_sum[d], el);
    atomicAdd(&g_deg[d], 1.f);
}

// ---------------------------------------------------------------------------
// K5: per-node denom: denom = seg_sum + (E - deg) * exp(-m)
// ---------------------------------------------------------------------------
__global__ void k_node(int N, float Ef) {
    int i = blockIdx.x * blockDim.x + threadIdx.x;
    if (i >= N) return;
    float denom = g_sum[i] + (Ef - g_deg[i]) * __expf(-g_m[i]);
    g_invd[i] = 1.f / denom;
}

// ---------------------------------------------------------------------------
// K6: aggregation: out[dst] += w * h[src]   (the heavy pass)
// 16 threads/edge, each owns one float4 chunk of the 64-wide feature.
// Gather fully coalesced (256 B per edge row); scatter via vectorized RED.
// ---------------------------------------------------------------------------
__global__ void k_agg(float* __restrict__ out, int E) {
    long long t = (long long)blockIdx.x * blockDim.x + threadIdx.x;
    int e = (int)(t >> 4);
    if (e >= E) return;
    int c = (int)(t & 15);
    int s = g_src[e];
    int d = g_dst[e];
    float w = g_logit[e] * g_invd[d];    // g_logit holds exp_l now
    const float4* h4 = (const float4*)g_h;
    float4 hv = h4[(size_t)s * 16 + c];
    float vx = w * hv.x, vy = w * hv.y, vz = w * hv.z, vw = w * hv.w;
    float* addr = out + (size_t)d * F_OUT + c * 4;
    asm volatile("red.global.add.v4.f32 [%0], {%1, %2, %3, %4};"
                 :: "l"(addr), "f"(vx), "f"(vy), "f"(vz), "f"(vw)
                 : "memory");
}

// ---------------------------------------------------------------------------
// K7: elementwise ELU over the output (float4 vectorized)
// ---------------------------------------------------------------------------
__global__ void k_elu(float* __restrict__ out, int n4) {
    int i = blockIdx.x * blockDim.x + threadIdx.x;
    if (i >= n4) return;
    float4 v = ((float4*)out)[i];
    v.x = (v.x > 0.f) ? v.x : expm1f(v.x);
    v.y = (v.y > 0.f) ? v.y : expm1f(v.y);
    v.z = (v.z > 0.f) ? v.z : expm1f(v.z);
    v.w = (v.w > 0.f) ? v.w : expm1f(v.w);
    ((float4*)out)[i] = v;
}

// ---------------------------------------------------------------------------
// Launch. Inputs identified by element count (robust to ordering):
//   x: N*128 = 6,400,000   edge_index: 2*E = 1,600,000   W: 8192   att: 128
// ---------------------------------------------------------------------------
extern "C" void kernel_launch(void* const* d_in, const int* in_sizes, int n_in,
                              void* d_out, int out_size) {
    const float* x   = nullptr;
    const void*  ei  = nullptr;
    const float* W   = nullptr;
    const float* att = nullptr;
    int N = NMAX, E = EMAX;

    // Identify inputs by size: largest = x, second = edge_index, then W, att.
    int order[8];
    for (int i = 0; i < n_in; i++) order[i] = i;
    for (int i = 0; i < n_in; i++)
        for (int j = i + 1; j < n_in; j++)
            if (in_sizes[order[j]] > in_sizes[order[i]]) {
                int tmp = order[i]; order[i] = order[j]; order[j] = tmp;
            }
    x   = (const float*)d_in[order[0]];
    ei  = (const void*) d_in[order[1]];
    W   = (const float*)d_in[order[2]];
    att = (const float*)d_in[order[3]];
    N = in_sizes[order[0]] / F_IN;       // 50000
    E = in_sizes[order[1]] / 2;          // 800000

    cudaMemsetAsync(d_out, 0, (size_t)out_size * sizeof(float));

    k_zero  <<<(N + 255) / 256, 256>>>(N);
    k_detect<<<1, 256>>>((const unsigned int*)ei);
    k_norm  <<<(E + 255) / 256, 256>>>(ei, E);
    k_gemm  <<<(N + 15) / 16, 256>>>(x, W, N);
    k_alpha <<<((N * 32) + 255) / 256, 256>>>(att, N);
    k_edge1 <<<(E + 255) / 256, 256>>>(E);
    k_edge2 <<<(E + 255) / 256, 256>>>(E);
    k_node  <<<(N + 255) / 256, 256>>>(N, (float)E);
    {
        long long total = (long long)E * 16;
        int blocks = (int)((total + 255) / 256);
        k_agg<<<blocks, 256>>>(d_out ? (float*)d_out : nullptr, E);
    }
    k_elu   <<<((N * 16) + 255) / 256, 256>>>((float*)d_out, N * 16);
}

// round 3
// speedup vs baseline: 1.2287x; 1.2287x over previous
#include <cuda_runtime.h>
#include <cuda_bf16.h>

#define NMAX 50000
#define EMAX 800000
#define F_IN 128
#define F_OUT 64

// ---- device scratch (no allocations allowed) ----
__device__ float g_h[NMAX * F_OUT];          // h = x @ W
__device__ float g_as[NMAX];                 // h . a1
__device__ float g_ad[NMAX];                 // h . a2
__device__ float g_m[NMAX];                  // max(seg_max, 0)
__device__ float g_sum[NMAX];                // segment sum of exp
__device__ float g_deg[NMAX];                // degree (float)
__device__ float g_invd[NMAX];               // 1/denom
__device__ float g_logit[EMAX];              // logit, then overwritten with exp_l
__device__ int   g_src[EMAX];                // normalized src indices (int32)
__device__ int   g_dst[EMAX];                // normalized dst indices (int32)
__device__ int   g_flag;                     // 0 = edge buffer is int64, nonzero = int32

// ---------------------------------------------------------------------------
// K0: zero the per-node accumulators + the dtype flag
// ---------------------------------------------------------------------------
__global__ void k_zero(int N) {
    int i = blockIdx.x * blockDim.x + threadIdx.x;
    if (i == 0) g_flag = 0;
    if (i < N) {
        g_m[i] = 0.f;
        g_sum[i] = 0.f;
        g_deg[i] = 0.f;
    }
}

// ---------------------------------------------------------------------------
// K-detect: int64 vs int32 edge buffer (odd 32-bit words all zero => int64)
// ---------------------------------------------------------------------------
__global__ void k_detect(const unsigned int* __restrict__ raw) {
    int t = threadIdx.x;                    // 256 threads, 1 block
    if (raw[2 * t + 1] != 0u)
        atomicOr(&g_flag, 1);
}

// ---------------------------------------------------------------------------
// K-norm: materialize int32 src/dst regardless of source dtype.
// ---------------------------------------------------------------------------
__global__ void k_norm(const void* __restrict__ raw, int E) {
    int e = blockIdx.x * blockDim.x + threadIdx.x;
    if (e >= E) return;
    int s, d;
    if (g_flag == 0) {                      // int64 source
        const long long* p = (const long long*)raw;
        s = (int)p[e];
        d = (int)p[E + e];
    } else {                                // int32 source
        const int* p = (const int*)raw;
        s = p[e];
        d = p[E + e];
    }
    g_src[e] = s;
    g_dst[e] = d;
}

// ---------------------------------------------------------------------------
// K1: h = x @ W  via register-blocked f32x2 FMA (FFMA2).
// Block: 128 threads, TILE_M = 128 rows, all 64 cols.
// Thread tile: 8 rows x 8 cols; acc held as f32x2 (1 row x 2 cols) pairs.
// Dynamic smem: Ws [128][64] (32KB) + xs transposed [128][132] (67.6KB).
// Per k per thread: 2 LDS.128 (a rows) + 2 LDS.128 (b cols, direct f32x2)
//                   + 8 mov-pack + 32 fma.rn.f32x2  -> FMA-pipe bound.
// ---------------------------------------------------------------------------
#define XS_PITCH 132   // pad: 16B-aligned rows (132%4==0), write stride 132%32=4 (mild)

__global__ void __launch_bounds__(128, 2)
k_gemm(const float* __restrict__ x, const float* __restrict__ W, int N) {
    extern __shared__ float smem[];
    float* Ws = smem;                        // [128][64]
    float* xs = smem + F_IN * F_OUT;         // [128][XS_PITCH]
    int tid = threadIdx.x;

    // Stage W (row-major [k][64]) as float4
    const float4* W4 = (const float4*)W;
    #pragma unroll
    for (int i = tid; i < F_IN * F_OUT / 4; i += 128)
        ((float4*)Ws)[i] = W4[i];

    // Stage x tile transposed: xs[k][r]
    int row0 = blockIdx.x * 128;
    for (int i = tid; i < 128 * F_IN; i += 128) {
        int r = i >> 7;          // 0..127
        int k = i & 127;         // coalesced gmem along k
        int gr = row0 + r;
        float v = (gr < N) ? x[(size_t)gr * F_IN + k] : 0.f;
        xs[k * XS_PITCH + r] = v;
    }
    __syncthreads();

    int trow = tid >> 3;         // 0..15
    int tcol = tid & 7;          // 0..7
    int r0 = trow * 8;
    int c0 = tcol * 8;

    unsigned long long acc[8][4];
    #pragma unroll
    for (int i = 0; i < 8; i++)
        #pragma unroll
        for (int j = 0; j < 4; j++) acc[i][j] = 0ULL;

    #pragma unroll 4
    for (int k = 0; k < F_IN; k++) {
        // b: 8 consecutive W cols -> 4 f32x2, loaded directly (no pack)
        ulonglong2 b01 = *(const ulonglong2*)&Ws[k * F_OUT + c0];
        ulonglong2 b23 = *(const ulonglong2*)&Ws[k * F_OUT + c0 + 4];
        unsigned long long b0 = b01.x, b1 = b01.y, b2 = b23.x, b3 = b23.y;
        // a: 8 consecutive rows of the transposed x tile
        float4 a03 = *(const float4*)&xs[k * XS_PITCH + r0];
        float4 a47 = *(const float4*)&xs[k * XS_PITCH + r0 + 4];
        float av[8] = {a03.x, a03.y, a03.z, a03.w, a47.x, a47.y, a47.z, a47.w};
        #pragma unroll
        for (int i = 0; i < 8; i++) {
            unsigned long long a2;
            asm("mov.b64 %0, {%1, %1};" : "=l"(a2) : "f"(av[i]));
            asm("fma.rn.f32x2 %0, %1, %2, %0;" : "+l"(acc[i][0]) : "l"(a2), "l"(b0));
            asm("fma.rn.f32x2 %0, %1, %2, %0;" : "+l"(acc[i][1]) : "l"(a2), "l"(b1));
            asm("fma.rn.f32x2 %0, %1, %2, %0;" : "+l"(acc[i][2]) : "l"(a2), "l"(b2));
            asm("fma.rn.f32x2 %0, %1, %2, %0;" : "+l"(acc[i][3]) : "l"(a2), "l"(b3));
        }
    }

    // Store 8 rows x 8 cols (2 x 16B per row)
    #pragma unroll
    for (int i = 0; i < 8; i++) {
        int row = row0 + r0 + i;
        if (row < N) {
            ulonglong2 s0; s0.x = acc[i][0]; s0.y = acc[i][1];
            ulonglong2 s1; s1.x = acc[i][2]; s1.y = acc[i][3];
            *(ulonglong2*)&g_h[(size_t)row * F_OUT + c0]     = s0;
            *(ulonglong2*)&g_h[(size_t)row * F_OUT + c0 + 4] = s1;
        }
    }
}

// ---------------------------------------------------------------------------
// K2: per-node attention coefficients: as = h.a1, ad = h.a2 (one warp/node)
// ---------------------------------------------------------------------------
__global__ void k_alpha(const float* __restrict__ att, int N) {
    int gt = blockIdx.x * blockDim.x + threadIdx.x;
    int node = gt >> 5;
    int lane = gt & 31;
    if (node >= N) return;
    float2 hv = *(const float2*)&g_h[(size_t)node * F_OUT + lane * 2];
    float a1x = att[lane * 2], a1y = att[lane * 2 + 1];
    float a2x = att[F_OUT + lane * 2], a2y = att[F_OUT + lane * 2 + 1];
    float s = hv.x * a1x + hv.y * a1y;
    float d = hv.x * a2x + hv.y * a2y;
    #pragma unroll
    for (int o = 16; o; o >>= 1) {
        s += __shfl_down_sync(0xFFFFFFFFu, s, o);
        d += __shfl_down_sync(0xFFFFFFFFu, d, o);
    }
    if (lane == 0) {
        g_as[node] = s;
        g_ad[node] = d;
    }
}

// ---------------------------------------------------------------------------
// K3: per-edge logit + segment max (atomicMax on int bits; m >= 0 invariant)
// ---------------------------------------------------------------------------
__global__ void k_edge1(int E) {
    int e = blockIdx.x * blockDim.x + threadIdx.x;
    if (e >= E) return;
    int s = g_src[e];
    int d = g_dst[e];
    float l = g_as[s] + g_ad[d];
    l = (l > 0.f) ? l : 0.2f * l;        // leaky_relu(0.2)
    g_logit[e] = l;
    if (l > 0.f)
        atomicMax((int*)&g_m[d], __float_as_int(l));
}

// ---------------------------------------------------------------------------
// K4: exp + segment sum + degree. Overwrites g_logit with exp_l.
// ---------------------------------------------------------------------------
__global__ void k_edge2(int E) {
    int e = blockIdx.x * blockDim.x + threadIdx.x;
    if (e >= E) return;
    int d = g_dst[e];
    float el = __expf(g_logit[e] - g_m[d]);
    g_logit[e] = el;
    atomicAdd(&g_sum[d], el);
    atomicAdd(&g_deg[d], 1.f);
}

// ---------------------------------------------------------------------------
// K5: per-node denom: denom = seg_sum + (E - deg) * exp(-m)
// ---------------------------------------------------------------------------
__global__ void k_node(int N, float Ef) {
    int i = blockIdx.x * blockDim.x + threadIdx.x;
    if (i >= N) return;
    float denom = g_sum[i] + (Ef - g_deg[i]) * __expf(-g_m[i]);
    g_invd[i] = 1.f / denom;
}

// ---------------------------------------------------------------------------
// K6: aggregation: out[dst] += w * h[src]
// 16 threads/edge, each owns one float4 chunk; vectorized RED scatter.
// ---------------------------------------------------------------------------
__global__ void k_agg(float* __restrict__ out, int E) {
    long long t = (long long)blockIdx.x * blockDim.x + threadIdx.x;
    int e = (int)(t >> 4);
    if (e >= E) return;
    int c = (int)(t & 15);
    int s = g_src[e];
    int d = g_dst[e];
    float w = g_logit[e] * g_invd[d];    // g_logit holds exp_l now
    const float4* h4 = (const float4*)g_h;
    float4 hv = h4[(size_t)s * 16 + c];
    float vx = w * hv.x, vy = w * hv.y, vz = w * hv.z, vw = w * hv.w;
    float* addr = out + (size_t)d * F_OUT + c * 4;
    asm volatile("red.global.add.v4.f32 [%0], {%1, %2, %3, %4};"
                 :: "l"(addr), "f"(vx), "f"(vy), "f"(vz), "f"(vw)
                 : "memory");
}

// ---------------------------------------------------------------------------
// K7: elementwise ELU over the output (float4 vectorized)
// ---------------------------------------------------------------------------
__global__ void k_elu(float* __restrict__ out, int n4) {
    int i = blockIdx.x * blockDim.x + threadIdx.x;
    if (i >= n4) return;
    float4 v = ((float4*)out)[i];
    v.x = (v.x > 0.f) ? v.x : expm1f(v.x);
    v.y = (v.y > 0.f) ? v.y : expm1f(v.y);
    v.z = (v.z > 0.f) ? v.z : expm1f(v.z);
    v.w = (v.w > 0.f) ? v.w : expm1f(v.w);
    ((float4*)out)[i] = v;
}

// ---------------------------------------------------------------------------
// Launch. Inputs identified by element count (robust to ordering):
//   x: N*128 = 6,400,000   edge_index: 2*E = 1,600,000   W: 8192   att: 128
// ---------------------------------------------------------------------------
extern "C" void kernel_launch(void* const* d_in, const int* in_sizes, int n_in,
                              void* d_out, int out_size) {
    int order[8];
    for (int i = 0; i < n_in; i++) order[i] = i;
    for (int i = 0; i < n_in; i++)
        for (int j = i + 1; j < n_in; j++)
            if (in_sizes[order[j]] > in_sizes[order[i]]) {
                int tmp = order[i]; order[i] = order[j]; order[j] = tmp;
            }
    const float* x   = (const float*)d_in[order[0]];
    const void*  ei  = (const void*) d_in[order[1]];
    const float* W   = (const float*)d_in[order[2]];
    const float* att = (const float*)d_in[order[3]];
    int N = in_sizes[order[0]] / F_IN;       // 50000
    int E = in_sizes[order[1]] / 2;          // 800000

    cudaMemsetAsync(d_out, 0, (size_t)out_size * sizeof(float));

    int gemm_smem = (F_IN * F_OUT + F_IN * XS_PITCH) * (int)sizeof(float);  // ~100KB
    static int attr_done = 0;
    if (!attr_done) {
        cudaFuncSetAttribute(k_gemm, cudaFuncAttributeMaxDynamicSharedMemorySize, gemm_smem);
        attr_done = 1;
    }

    k_zero  <<<(N + 255) / 256, 256>>>(N);
    k_detect<<<1, 256>>>((const unsigned int*)ei);
    k_norm  <<<(E + 255) / 256, 256>>>(ei, E);
    k_gemm  <<<(N + 127) / 128, 128, gemm_smem>>>(x, W, N);
    k_alpha <<<((N * 32) + 255) / 256, 256>>>(att, N);
    k_edge1 <<<(E + 255) / 256, 256>>>(E);
    k_edge2 <<<(E + 255) / 256, 256>>>(E);
    k_node  <<<(N + 255) / 256, 256>>>(N, (float)E);
    {
        long long total = (long long)E * 16;
        int blocks = (int)((total + 255) / 256);
        k_agg<<<blocks, 256>>>((float*)d_out, E);
    }
    k_elu   <<<((N * 16) + 255) / 256, 256>>>((float*)d_out, N * 16);
}